// round 4
// baseline (speedup 1.0000x reference)
#include <cuda_runtime.h>
#include <cstdint>

#define NN 100000
#define NE 1000000
#define D  64
#define MP 3

// Scratch (__device__ globals per allocation-free rule)
__device__ float mg_h[(size_t)MP * NN * D];     // transformed features (76.8 MB)
__device__ float mg_dinv[MP * NN];              // 1/sqrt(deg)
__device__ int   mg_count[MP * NN];             // edges per dest node
__device__ int   mg_off[MP * NN];               // CSR start offsets
__device__ int   mg_ctr[MP * NN];               // running fill cursors
__device__ int   mg_srow[(size_t)MP * NE];      // binned source node ids
__device__ float mg_sew[(size_t)MP * NE];       // binned raw edge weights
__device__ int   mg_sh;                         // 0 = int32 edge idx, 1 = int64

// ---------------------------------------------------------------------------
// Dtype sniff: int64 little-endian node ids (<2^32) have zero high words at
// every odd int32 position. 256 random odd samples all-zero => int64.
// ---------------------------------------------------------------------------
__global__ void mz_sniff(const int* __restrict__ ei32) {
    int t = threadIdx.x;                 // one warp
    int nz = 0;
    for (int k = 0; k < 8; k++) {
        int s = (t * 8 + k) * 1009;      // < 258k, safely in-bounds either way
        nz |= (ei32[2 * s + 1] != 0);
    }
    unsigned b = __ballot_sync(0xffffffffu, nz);
    if (t == 0) mg_sh = (b == 0u) ? 1 : 0;
}

__device__ __forceinline__ int ld_idx(const int* p, size_t pos, int sh) {
    return p[pos << sh];                 // low word == value for both dtypes
}

// ---------------------------------------------------------------------------
__global__ void mz_zero() {
    int i = blockIdx.x * blockDim.x + threadIdx.x;
    if (i < MP * NN) mg_count[i] = 0;
}

// count[col]++  (int atomics only)
__global__ void mz_hist(const int* __restrict__ ei32) {
    int mp = blockIdx.y;
    int sh = mg_sh;
    size_t colbase = (size_t)mp * 2 * NE + NE;
    int* cnt = mg_count + (size_t)mp * NN;
    int stride = gridDim.x * blockDim.x;
    for (int e = blockIdx.x * blockDim.x + threadIdx.x; e < NE; e += stride) {
        int c = ld_idx(ei32, colbase + e, sh);
        atomicAdd(cnt + c, 1);
    }
}

// Exclusive scan of count -> off (and ctr copy). One block per metapath.
__global__ __launch_bounds__(1024) void mz_scan() {
    __shared__ int s[1024];
    __shared__ int carry;
    int mp = blockIdx.x;
    int t = threadIdx.x;
    if (t == 0) carry = 0;
    __syncthreads();
    const int* cnt = mg_count + (size_t)mp * NN;
    int* off = mg_off + (size_t)mp * NN;
    int* ctr = mg_ctr + (size_t)mp * NN;
    for (int base = 0; base < NN; base += 1024) {
        int i = base + t;
        int v = (i < NN) ? cnt[i] : 0;
        s[t] = v;
        __syncthreads();
        for (int d2 = 1; d2 < 1024; d2 <<= 1) {
            int add = (t >= d2) ? s[t - d2] : 0;
            __syncthreads();
            s[t] += add;
            __syncthreads();
        }
        int total = s[1023];
        if (i < NN) {
            int excl = carry + s[t] - v;
            off[i] = excl;
            ctr[i] = excl;
        }
        __syncthreads();
        if (t == 0) carry += total;
        __syncthreads();
    }
}

// Bin (row, ew) by dest node. Int atomics only.
__global__ void mz_fill(const int* __restrict__ ei32,
                        const float* __restrict__ ew) {
    int mp = blockIdx.y;
    int sh = mg_sh;
    size_t rowbase = (size_t)mp * 2 * NE;
    size_t colbase = rowbase + NE;
    const float* ewp = ew + (size_t)mp * NE;
    int* ctr = mg_ctr + (size_t)mp * NN;
    int* srow = mg_srow + (size_t)mp * NE;
    float* sew = mg_sew + (size_t)mp * NE;
    int stride = gridDim.x * blockDim.x;
    for (int e = blockIdx.x * blockDim.x + threadIdx.x; e < NE; e += stride) {
        int r = ld_idx(ei32, rowbase + e, sh);
        int c = ld_idx(ei32, colbase + e, sh);
        int pos = atomicAdd(ctr + c, 1);
        srow[pos] = r;
        sew[pos] = ewp[e];
    }
}

// deg[node] = sum of its bin's ew (warp per node, NO atomics) -> dinv
__global__ __launch_bounds__(256) void mz_deg() {
    int mp = blockIdx.y;
    int node = blockIdx.x * 8 + (threadIdx.x >> 5);
    if (node >= NN) return;
    int lane = threadIdx.x & 31;
    int start = mg_off[(size_t)mp * NN + node];
    int n = mg_count[(size_t)mp * NN + node];
    const float* sew = mg_sew + (size_t)mp * NE + start;
    float s = 0.f;
    for (int j = lane; j < n; j += 32) s += sew[j];
#pragma unroll
    for (int o = 16; o > 0; o >>= 1) s += __shfl_down_sync(0xffffffffu, s, o);
    if (lane == 0) {
        mg_dinv[(size_t)mp * NN + node] = (s > 0.f) ? rsqrtf(s) : 0.f;
    }
}

// ---------------------------------------------------------------------------
// h[mp] = x @ W[mp] : W column in registers, x tile in smem (broadcast reads)
// ---------------------------------------------------------------------------
#define ROWS_PER_BLK 128

__global__ __launch_bounds__(256) void mz_gemm(const float* __restrict__ x,
                                               const float* __restrict__ W) {
    __shared__ float sW[D * D];
    __shared__ float sx[ROWS_PER_BLK][D];
    int mp = blockIdx.y;
    int t = threadIdx.x;

    const float* Wm = W + (size_t)mp * D * D;
    for (int i = t; i < D * D; i += 256) sW[i] = Wm[i];
    __syncthreads();

    int d = t & 63;
    int r0 = t >> 6;
    float wcol[D];
#pragma unroll
    for (int k = 0; k < D; k++) wcol[k] = sW[k * D + d];

    int rowbase = blockIdx.x * ROWS_PER_BLK;
    const float4* x4 = (const float4*)(x + (size_t)rowbase * D);
    float4* sx4 = (float4*)sx;
    for (int i = t; i < ROWS_PER_BLK * D / 4; i += 256) {
        int row = rowbase + (i >> 4);
        if (row < NN) sx4[i] = x4[i];
    }
    __syncthreads();

    float* hout = mg_h + (size_t)mp * NN * D;
    for (int r = r0; r < ROWS_PER_BLK; r += 4) {
        int row = rowbase + r;
        if (row >= NN) break;
        const float* xr = sx[r];
        float acc = 0.f;
#pragma unroll
        for (int k = 0; k < D; k++) acc = fmaf(xr[k], wcol[k], acc);
        hout[(size_t)row * D + d] = acc;
    }
}

// ---------------------------------------------------------------------------
// Gather: warp per dest node, register accumulation, fused ReLU.
// norm = dinv[row]*ew*dinv[col] computed on the fly. No float atomics.
// ---------------------------------------------------------------------------
__global__ __launch_bounds__(256) void mz_gather(float* __restrict__ out,
                                                 int mp) {
    int node = blockIdx.x * 8 + (threadIdx.x >> 5);
    if (node >= NN) return;
    int lane = threadIdx.x & 31;
    const float* h = mg_h + (size_t)mp * NN * D;
    const float* dinv = mg_dinv + (size_t)mp * NN;
    int start = mg_off[(size_t)mp * NN + node];
    int n = mg_count[(size_t)mp * NN + node];
    const int* srow = mg_srow + (size_t)mp * NE + start;
    const float* sew = mg_sew + (size_t)mp * NE + start;
    float dc = dinv[node];

    float2 acc = make_float2(0.f, 0.f);
    int j = 0;
    for (; j + 2 <= n; j += 2) {
        int r0 = srow[j], r1 = srow[j + 1];
        float w0 = sew[j], w1 = sew[j + 1];
        float2 v0 = *(const float2*)(h + (size_t)r0 * D + lane * 2);
        float2 v1 = *(const float2*)(h + (size_t)r1 * D + lane * 2);
        float n0 = dinv[r0] * w0 * dc;
        float n1 = dinv[r1] * w1 * dc;
        acc.x = fmaf(v0.x, n0, acc.x);
        acc.y = fmaf(v0.y, n0, acc.y);
        acc.x = fmaf(v1.x, n1, acc.x);
        acc.y = fmaf(v1.y, n1, acc.y);
    }
    if (j < n) {
        int r = srow[j];
        float nm = dinv[r] * sew[j] * dc;
        float2 v = *(const float2*)(h + (size_t)r * D + lane * 2);
        acc.x = fmaf(v.x, nm, acc.x);
        acc.y = fmaf(v.y, nm, acc.y);
    }
    float2 o;
    o.x = fmaxf(acc.x, 0.f);
    o.y = fmaxf(acc.y, 0.f);
    *(float2*)(out + (size_t)mp * NN * D + (size_t)node * D + lane * 2) = o;
}

// ---------------------------------------------------------------------------
extern "C" void kernel_launch(void* const* d_in, const int* in_sizes, int n_in,
                              void* d_out, int out_size) {
    const float* x = (const float*)d_in[0];        // [NN, D]
    const float* W = (const float*)d_in[1];        // [MP, D, D]
    const int* ei32 = (const int*)d_in[2];         // [MP, 2, NE] int32 OR int64
    const float* ew = (const float*)d_in[3];       // [MP, NE]
    float* out = (float*)d_out;                    // [MP, NN, D]

    mz_sniff<<<1, 32>>>(ei32);
    mz_zero<<<(MP * NN + 255) / 256, 256>>>();
    mz_hist<<<dim3(512, MP), 256>>>(ei32);
    mz_scan<<<MP, 1024>>>();
    mz_fill<<<dim3(512, MP), 256>>>(ei32, ew);
    mz_deg<<<dim3((NN + 7) / 8, MP), 256>>>();
    mz_gemm<<<dim3((NN + ROWS_PER_BLK - 1) / ROWS_PER_BLK, MP), 256>>>(x, W);

    // per-metapath sequential: keeps h[mp] (25.6 MB) L2-resident during gather
    for (int mp = 0; mp < MP; mp++) {
        mz_gather<<<(NN + 7) / 8, 256>>>(out, mp);
    }
}

// round 5
// speedup vs baseline: 1.4219x; 1.4219x over previous
#include <cuda_runtime.h>
#include <cstdint>

#define NN 100000
#define NE 1000000
#define D  64
#define MP 3

#define TILE 2048
#define NT ((NN + TILE - 1) / TILE)   // 49 tiles per metapath

// Scratch (__device__ globals per allocation-free rule)
__device__ float mg_h[(size_t)MP * NN * D];     // transformed features (76.8 MB)
__device__ float mg_deg[MP * NN];               // deg -> dinv in place
__device__ int   mg_count[MP * NN];             // edges per dest node
__device__ int   mg_off[MP * NN];               // CSR start offsets
__device__ int   mg_ctr[MP * NN];               // running fill cursors
__device__ int   mg_srow[(size_t)MP * NE];      // binned source node ids
__device__ float mg_sew[(size_t)MP * NE];       // binned raw edge weights
__device__ int   mg_tiletot[MP * NT];           // per-tile counts
__device__ int   mg_tileoff[MP * NT];           // exclusive tile offsets
__device__ int   mg_sh;                         // 0 = int32 edge idx, 1 = int64

// ---------------------------------------------------------------------------
// Dtype sniff: int64 node ids (<2^32) have zero high words at odd positions.
// ---------------------------------------------------------------------------
__global__ void mz_sniff(const int* __restrict__ ei32) {
    int t = threadIdx.x;
    int nz = 0;
    for (int k = 0; k < 8; k++) {
        int s = (t * 8 + k) * 1009;
        nz |= (ei32[2 * s + 1] != 0);
    }
    unsigned b = __ballot_sync(0xffffffffu, nz);
    if (t == 0) mg_sh = (b == 0u) ? 1 : 0;
}

__device__ __forceinline__ int ld_idx(const int* p, size_t pos, int sh) {
    return p[pos << sh];
}

// ---------------------------------------------------------------------------
__global__ void mz_zero() {
    int i = blockIdx.x * blockDim.x + threadIdx.x;
    if (i < MP * NN) { mg_count[i] = 0; mg_deg[i] = 0.f; }
}

// Fused: count[col]++ (int) and deg[col] += ew (f32 red, spread addresses)
__global__ void mz_hist(const int* __restrict__ ei32,
                        const float* __restrict__ ew) {
    int mp = blockIdx.y;
    int sh = mg_sh;
    size_t colbase = (size_t)mp * 2 * NE + NE;
    const float* ewp = ew + (size_t)mp * NE;
    int* cnt = mg_count + (size_t)mp * NN;
    float* deg = mg_deg + (size_t)mp * NN;
    int stride = gridDim.x * blockDim.x;
    for (int e = blockIdx.x * blockDim.x + threadIdx.x; e < NE; e += stride) {
        int c = ld_idx(ei32, colbase + e, sh);
        atomicAdd(cnt + c, 1);
        atomicAdd(deg + c, ewp[e]);
    }
}

__global__ void mz_dinv() {
    int i = blockIdx.x * blockDim.x + threadIdx.x;
    if (i < MP * NN) {
        float d = mg_deg[i];
        mg_deg[i] = (d > 0.f) ? rsqrtf(d) : 0.f;
    }
}

// ---------------------------------------------------------------------------
// 3-phase decoupled scan of mg_count -> mg_off (exclusive), mg_ctr copy.
// ---------------------------------------------------------------------------
// Phase A: each block scans a TILE (256 thr x 8 elems), writes tile-local
// exclusive scan + tile total.
__global__ __launch_bounds__(256) void mz_scanA() {
    __shared__ int wtot[8];
    __shared__ int wpre[8];
    int mp = blockIdx.y;
    int tile = blockIdx.x;
    int t = threadIdx.x;
    int lane = t & 31;
    int warp = t >> 5;
    const int* cnt = mg_count + (size_t)mp * NN;
    int* off = mg_off + (size_t)mp * NN;

    int base = tile * TILE + t * 8;
    int v[8];
#pragma unroll
    for (int k = 0; k < 8; k++) {
        int i = base + k;
        v[k] = (i < NN) ? cnt[i] : 0;
    }
    int mysum = 0;
#pragma unroll
    for (int k = 0; k < 8; k++) mysum += v[k];

    // inclusive warp scan of mysum
    int inc = mysum;
#pragma unroll
    for (int o = 1; o < 32; o <<= 1) {
        int n = __shfl_up_sync(0xffffffffu, inc, o);
        if (lane >= o) inc += n;
    }
    if (lane == 31) wtot[warp] = inc;
    __syncthreads();
    if (t == 0) {
        int run = 0;
#pragma unroll
        for (int w = 0; w < 8; w++) { wpre[w] = run; run += wtot[w]; }
        mg_tiletot[mp * NT + tile] = run;
    }
    __syncthreads();

    int excl = wpre[warp] + inc - mysum;   // tile-local exclusive prefix
#pragma unroll
    for (int k = 0; k < 8; k++) {
        int i = base + k;
        if (i < NN) off[i] = excl;
        excl += v[k];
    }
}

// Phase B: one block per metapath scans NT (<=64) tile totals.
__global__ __launch_bounds__(64) void mz_scanB() {
    __shared__ int s[64];
    int mp = blockIdx.x;
    int t = threadIdx.x;
    s[t] = (t < NT) ? mg_tiletot[mp * NT + t] : 0;
    __syncthreads();
    for (int d2 = 1; d2 < 64; d2 <<= 1) {
        int add = (t >= d2) ? s[t - d2] : 0;
        __syncthreads();
        s[t] += add;
        __syncthreads();
    }
    if (t < NT) mg_tileoff[mp * NT + t] = s[t] - mg_tiletot[mp * NT + t];
}

// Phase C: add tile offsets; produce final off + ctr copy.
__global__ __launch_bounds__(256) void mz_scanC() {
    int mp = blockIdx.y;
    int tile = blockIdx.x;
    int t = threadIdx.x;
    int toff = mg_tileoff[mp * NT + tile];
    int* off = mg_off + (size_t)mp * NN;
    int* ctr = mg_ctr + (size_t)mp * NN;
    int base = tile * TILE + t * 8;
#pragma unroll
    for (int k = 0; k < 8; k++) {
        int i = base + k;
        if (i < NN) {
            int v = off[i] + toff;
            off[i] = v;
            ctr[i] = v;
        }
    }
}

// ---------------------------------------------------------------------------
// Bin (row, ew) by dest node. Int atomics only.
// ---------------------------------------------------------------------------
__global__ void mz_fill(const int* __restrict__ ei32,
                        const float* __restrict__ ew) {
    int mp = blockIdx.y;
    int sh = mg_sh;
    size_t rowbase = (size_t)mp * 2 * NE;
    size_t colbase = rowbase + NE;
    const float* ewp = ew + (size_t)mp * NE;
    int* ctr = mg_ctr + (size_t)mp * NN;
    int* srow = mg_srow + (size_t)mp * NE;
    float* sew = mg_sew + (size_t)mp * NE;
    int stride = gridDim.x * blockDim.x;
    for (int e = blockIdx.x * blockDim.x + threadIdx.x; e < NE; e += stride) {
        int r = ld_idx(ei32, rowbase + e, sh);
        int c = ld_idx(ei32, colbase + e, sh);
        int pos = atomicAdd(ctr + c, 1);
        srow[pos] = r;
        sew[pos] = ewp[e];
    }
}

// ---------------------------------------------------------------------------
// h[mp] = x @ W[mp]
// ---------------------------------------------------------------------------
#define ROWS_PER_BLK 128

__global__ __launch_bounds__(256) void mz_gemm(const float* __restrict__ x,
                                               const float* __restrict__ W) {
    __shared__ float sW[D * D];
    __shared__ float sx[ROWS_PER_BLK][D];
    int mp = blockIdx.y;
    int t = threadIdx.x;

    const float* Wm = W + (size_t)mp * D * D;
    for (int i = t; i < D * D; i += 256) sW[i] = Wm[i];
    __syncthreads();

    int d = t & 63;
    int r0 = t >> 6;
    float wcol[D];
#pragma unroll
    for (int k = 0; k < D; k++) wcol[k] = sW[k * D + d];

    int rowbase = blockIdx.x * ROWS_PER_BLK;
    const float4* x4 = (const float4*)(x + (size_t)rowbase * D);
    float4* sx4 = (float4*)sx;
    for (int i = t; i < ROWS_PER_BLK * D / 4; i += 256) {
        int row = rowbase + (i >> 4);
        if (row < NN) sx4[i] = x4[i];
    }
    __syncthreads();

    float* hout = mg_h + (size_t)mp * NN * D;
    for (int r = r0; r < ROWS_PER_BLK; r += 4) {
        int row = rowbase + r;
        if (row >= NN) break;
        const float* xr = sx[r];
        float acc = 0.f;
#pragma unroll
        for (int k = 0; k < D; k++) acc = fmaf(xr[k], wcol[k], acc);
        hout[(size_t)row * D + d] = acc;
    }
}

// ---------------------------------------------------------------------------
// Gather: warp per dest node, register accumulation, fused ReLU.
// ---------------------------------------------------------------------------
__global__ __launch_bounds__(256) void mz_gather(float* __restrict__ out,
                                                 int mp) {
    int node = blockIdx.x * 8 + (threadIdx.x >> 5);
    if (node >= NN) return;
    int lane = threadIdx.x & 31;
    const float* h = mg_h + (size_t)mp * NN * D;
    const float* dinv = mg_deg + (size_t)mp * NN;
    int start = mg_off[(size_t)mp * NN + node];
    int n = mg_count[(size_t)mp * NN + node];
    const int* srow = mg_srow + (size_t)mp * NE + start;
    const float* sew = mg_sew + (size_t)mp * NE + start;
    float dc = dinv[node];

    float2 acc = make_float2(0.f, 0.f);
    int j = 0;
    for (; j + 2 <= n; j += 2) {
        int r0 = srow[j], r1 = srow[j + 1];
        float w0 = sew[j], w1 = sew[j + 1];
        float2 v0 = *(const float2*)(h + (size_t)r0 * D + lane * 2);
        float2 v1 = *(const float2*)(h + (size_t)r1 * D + lane * 2);
        float n0 = dinv[r0] * w0 * dc;
        float n1 = dinv[r1] * w1 * dc;
        acc.x = fmaf(v0.x, n0, acc.x);
        acc.y = fmaf(v0.y, n0, acc.y);
        acc.x = fmaf(v1.x, n1, acc.x);
        acc.y = fmaf(v1.y, n1, acc.y);
    }
    if (j < n) {
        int r = srow[j];
        float nm = dinv[r] * sew[j] * dc;
        float2 v = *(const float2*)(h + (size_t)r * D + lane * 2);
        acc.x = fmaf(v.x, nm, acc.x);
        acc.y = fmaf(v.y, nm, acc.y);
    }
    float2 o;
    o.x = fmaxf(acc.x, 0.f);
    o.y = fmaxf(acc.y, 0.f);
    *(float2*)(out + (size_t)mp * NN * D + (size_t)node * D + lane * 2) = o;
}

// ---------------------------------------------------------------------------
extern "C" void kernel_launch(void* const* d_in, const int* in_sizes, int n_in,
                              void* d_out, int out_size) {
    const float* x = (const float*)d_in[0];        // [NN, D]
    const float* W = (const float*)d_in[1];        // [MP, D, D]
    const int* ei32 = (const int*)d_in[2];         // [MP, 2, NE] (int32 or int64)
    const float* ew = (const float*)d_in[3];       // [MP, NE]
    float* out = (float*)d_out;                    // [MP, NN, D]

    mz_sniff<<<1, 32>>>(ei32);
    mz_zero<<<(MP * NN + 255) / 256, 256>>>();
    mz_hist<<<dim3(512, MP), 256>>>(ei32, ew);
    mz_dinv<<<(MP * NN + 255) / 256, 256>>>();
    mz_scanA<<<dim3(NT, MP), 256>>>();
    mz_scanB<<<MP, 64>>>();
    mz_scanC<<<dim3(NT, MP), 256>>>();
    mz_fill<<<dim3(512, MP), 256>>>(ei32, ew);
    mz_gemm<<<dim3((NN + ROWS_PER_BLK - 1) / ROWS_PER_BLK, MP), 256>>>(x, W);

    // per-metapath sequential: keeps h[mp] (25.6 MB) L2-resident during gather
    for (int mp = 0; mp < MP; mp++) {
        mz_gather<<<(NN + 7) / 8, 256>>>(out, mp);
    }
}

// round 6
// speedup vs baseline: 1.5445x; 1.0862x over previous
#include <cuda_runtime.h>
#include <cstdint>

#define NN 100000
#define NE 1000000
#define D  64
#define MP 3

#define TILE 2048
#define NT ((NN + TILE - 1) / TILE)

// Scratch (__device__ globals per allocation-free rule)
__device__ float mg_h[(size_t)MP * NN * D];     // transformed features (76.8 MB)
__device__ float mg_deg[MP * NN];               // deg -> dinv in place
__device__ int   mg_count[MP * NN];             // edges per dest node
__device__ int   mg_off[MP * NN];               // CSR start offsets
__device__ int   mg_ctr[MP * NN];               // running fill cursors
__device__ int2  mg_edge[(size_t)MP * NE];      // packed (src row, norm bits)
__device__ int   mg_tiletot[MP * NT];
__device__ int   mg_tileoff[MP * NT];
__device__ int   mg_sh;                         // 0 = int32 idx, 1 = int64

// ---------------------------------------------------------------------------
__global__ void mz_sniff(const int* __restrict__ ei32) {
    int t = threadIdx.x;
    int nz = 0;
    for (int k = 0; k < 8; k++) {
        int s = (t * 8 + k) * 1009;
        nz |= (ei32[2 * s + 1] != 0);
    }
    unsigned b = __ballot_sync(0xffffffffu, nz);
    if (t == 0) mg_sh = (b == 0u) ? 1 : 0;
}

__device__ __forceinline__ int ld_idx(const int* p, size_t pos, int sh) {
    return p[pos << sh];
}

// ---------------------------------------------------------------------------
__global__ void mz_zero() {
    int i = blockIdx.x * blockDim.x + threadIdx.x;
    if (i < MP * NN) { mg_count[i] = 0; mg_deg[i] = 0.f; }
}

// Fused: count[col]++ (int) and deg[col] += ew (f32)
__global__ void mz_hist(const int* __restrict__ ei32,
                        const float* __restrict__ ew) {
    int mp = blockIdx.y;
    int sh = mg_sh;
    size_t colbase = (size_t)mp * 2 * NE + NE;
    const float* ewp = ew + (size_t)mp * NE;
    int* cnt = mg_count + (size_t)mp * NN;
    float* deg = mg_deg + (size_t)mp * NN;
    int stride = gridDim.x * blockDim.x;
    for (int e = blockIdx.x * blockDim.x + threadIdx.x; e < NE; e += stride) {
        int c = ld_idx(ei32, colbase + e, sh);
        atomicAdd(cnt + c, 1);
        atomicAdd(deg + c, ewp[e]);
    }
}

__global__ void mz_dinv() {
    int i = blockIdx.x * blockDim.x + threadIdx.x;
    if (i < MP * NN) {
        float d = mg_deg[i];
        mg_deg[i] = (d > 0.f) ? rsqrtf(d) : 0.f;
    }
}

// ---------------------------------------------------------------------------
// 3-phase decoupled scan: count -> off (exclusive) + ctr copy
// ---------------------------------------------------------------------------
__global__ __launch_bounds__(256) void mz_scanA() {
    __shared__ int wtot[8];
    __shared__ int wpre[8];
    int mp = blockIdx.y;
    int tile = blockIdx.x;
    int t = threadIdx.x;
    int lane = t & 31;
    int warp = t >> 5;
    const int* cnt = mg_count + (size_t)mp * NN;
    int* off = mg_off + (size_t)mp * NN;

    int base = tile * TILE + t * 8;
    int v[8];
#pragma unroll
    for (int k = 0; k < 8; k++) {
        int i = base + k;
        v[k] = (i < NN) ? cnt[i] : 0;
    }
    int mysum = 0;
#pragma unroll
    for (int k = 0; k < 8; k++) mysum += v[k];

    int inc = mysum;
#pragma unroll
    for (int o = 1; o < 32; o <<= 1) {
        int n = __shfl_up_sync(0xffffffffu, inc, o);
        if (lane >= o) inc += n;
    }
    if (lane == 31) wtot[warp] = inc;
    __syncthreads();
    if (t == 0) {
        int run = 0;
#pragma unroll
        for (int w = 0; w < 8; w++) { wpre[w] = run; run += wtot[w]; }
        mg_tiletot[mp * NT + tile] = run;
    }
    __syncthreads();

    int excl = wpre[warp] + inc - mysum;
#pragma unroll
    for (int k = 0; k < 8; k++) {
        int i = base + k;
        if (i < NN) off[i] = excl;
        excl += v[k];
    }
}

__global__ __launch_bounds__(64) void mz_scanB() {
    __shared__ int s[64];
    int mp = blockIdx.x;
    int t = threadIdx.x;
    s[t] = (t < NT) ? mg_tiletot[mp * NT + t] : 0;
    __syncthreads();
    for (int d2 = 1; d2 < 64; d2 <<= 1) {
        int add = (t >= d2) ? s[t - d2] : 0;
        __syncthreads();
        s[t] += add;
        __syncthreads();
    }
    if (t < NT) mg_tileoff[mp * NT + t] = s[t] - mg_tiletot[mp * NT + t];
}

__global__ __launch_bounds__(256) void mz_scanC() {
    int mp = blockIdx.y;
    int tile = blockIdx.x;
    int t = threadIdx.x;
    int toff = mg_tileoff[mp * NT + tile];
    int* off = mg_off + (size_t)mp * NN;
    int* ctr = mg_ctr + (size_t)mp * NN;
    int base = tile * TILE + t * 8;
#pragma unroll
    for (int k = 0; k < 8; k++) {
        int i = base + k;
        if (i < NN) {
            int v = off[i] + toff;
            off[i] = v;
            ctr[i] = v;
        }
    }
}

// ---------------------------------------------------------------------------
// Bin edges: store packed (row, norm) with norm fully precomputed.
// One scattered STG.64 per edge.
// ---------------------------------------------------------------------------
__global__ void mz_fill(const int* __restrict__ ei32,
                        const float* __restrict__ ew) {
    int mp = blockIdx.y;
    int sh = mg_sh;
    size_t rowbase = (size_t)mp * 2 * NE;
    size_t colbase = rowbase + NE;
    const float* ewp = ew + (size_t)mp * NE;
    const float* dinv = mg_deg + (size_t)mp * NN;
    int* ctr = mg_ctr + (size_t)mp * NN;
    int2* edges = mg_edge + (size_t)mp * NE;
    int stride = gridDim.x * blockDim.x;
    for (int e = blockIdx.x * blockDim.x + threadIdx.x; e < NE; e += stride) {
        int r = ld_idx(ei32, rowbase + e, sh);
        int c = ld_idx(ei32, colbase + e, sh);
        float nm = dinv[r] * ewp[e] * dinv[c];
        int pos = atomicAdd(ctr + c, 1);
        edges[pos] = make_int2(r, __float_as_int(nm));
    }
}

// ---------------------------------------------------------------------------
// h[mp] = x @ W[mp]
// ---------------------------------------------------------------------------
#define ROWS_PER_BLK 128

__global__ __launch_bounds__(256) void mz_gemm(const float* __restrict__ x,
                                               const float* __restrict__ W) {
    __shared__ float sW[D * D];
    __shared__ float sx[ROWS_PER_BLK][D];
    int mp = blockIdx.y;
    int t = threadIdx.x;

    const float* Wm = W + (size_t)mp * D * D;
    for (int i = t; i < D * D; i += 256) sW[i] = Wm[i];
    __syncthreads();

    int d = t & 63;
    int r0 = t >> 6;
    float wcol[D];
#pragma unroll
    for (int k = 0; k < D; k++) wcol[k] = sW[k * D + d];

    int rowbase = blockIdx.x * ROWS_PER_BLK;
    const float4* x4 = (const float4*)(x + (size_t)rowbase * D);
    float4* sx4 = (float4*)sx;
    for (int i = t; i < ROWS_PER_BLK * D / 4; i += 256) {
        int row = rowbase + (i >> 4);
        if (row < NN) sx4[i] = x4[i];
    }
    __syncthreads();

    float* hout = mg_h + (size_t)mp * NN * D;
    for (int r = r0; r < ROWS_PER_BLK; r += 4) {
        int row = rowbase + r;
        if (row >= NN) break;
        const float* xr = sx[r];
        float acc = 0.f;
#pragma unroll
        for (int k = 0; k < D; k++) acc = fmaf(xr[k], wcol[k], acc);
        hout[(size_t)row * D + d] = acc;
    }
}

// ---------------------------------------------------------------------------
// Gather: warp per dest node; per edge one int2 load + one float2 h load.
// 4-wide unroll for MLP. Fused ReLU, single coalesced store.
// ---------------------------------------------------------------------------
__global__ __launch_bounds__(256) void mz_gather(float* __restrict__ out,
                                                 int mp) {
    int node = blockIdx.x * 8 + (threadIdx.x >> 5);
    if (node >= NN) return;
    int lane = threadIdx.x & 31;
    const float* h = mg_h + (size_t)mp * NN * D;
    int start = mg_off[(size_t)mp * NN + node];
    int n = mg_count[(size_t)mp * NN + node];
    const int2* edges = mg_edge + (size_t)mp * NE + start;

    float2 acc = make_float2(0.f, 0.f);
    int j = 0;
    for (; j + 4 <= n; j += 4) {
        int2 e0 = edges[j], e1 = edges[j + 1], e2 = edges[j + 2], e3 = edges[j + 3];
        float2 v0 = *(const float2*)(h + (size_t)e0.x * D + lane * 2);
        float2 v1 = *(const float2*)(h + (size_t)e1.x * D + lane * 2);
        float2 v2 = *(const float2*)(h + (size_t)e2.x * D + lane * 2);
        float2 v3 = *(const float2*)(h + (size_t)e3.x * D + lane * 2);
        float n0 = __int_as_float(e0.y), n1 = __int_as_float(e1.y);
        float n2 = __int_as_float(e2.y), n3 = __int_as_float(e3.y);
        acc.x = fmaf(v0.x, n0, acc.x); acc.y = fmaf(v0.y, n0, acc.y);
        acc.x = fmaf(v1.x, n1, acc.x); acc.y = fmaf(v1.y, n1, acc.y);
        acc.x = fmaf(v2.x, n2, acc.x); acc.y = fmaf(v2.y, n2, acc.y);
        acc.x = fmaf(v3.x, n3, acc.x); acc.y = fmaf(v3.y, n3, acc.y);
    }
    for (; j < n; j++) {
        int2 e = edges[j];
        float nm = __int_as_float(e.y);
        float2 v = *(const float2*)(h + (size_t)e.x * D + lane * 2);
        acc.x = fmaf(v.x, nm, acc.x);
        acc.y = fmaf(v.y, nm, acc.y);
    }
    float2 o;
    o.x = fmaxf(acc.x, 0.f);
    o.y = fmaxf(acc.y, 0.f);
    *(float2*)(out + (size_t)mp * NN * D + (size_t)node * D + lane * 2) = o;
}

// ---------------------------------------------------------------------------
extern "C" void kernel_launch(void* const* d_in, const int* in_sizes, int n_in,
                              void* d_out, int out_size) {
    const float* x = (const float*)d_in[0];
    const float* W = (const float*)d_in[1];
    const int* ei32 = (const int*)d_in[2];
    const float* ew = (const float*)d_in[3];
    float* out = (float*)d_out;

    mz_sniff<<<1, 32>>>(ei32);
    mz_zero<<<(MP * NN + 255) / 256, 256>>>();
    mz_hist<<<dim3(512, MP), 256>>>(ei32, ew);
    mz_dinv<<<(MP * NN + 255) / 256, 256>>>();
    mz_scanA<<<dim3(NT, MP), 256>>>();
    mz_scanB<<<MP, 64>>>();
    mz_scanC<<<dim3(NT, MP), 256>>>();
    mz_fill<<<dim3(512, MP), 256>>>(ei32, ew);
    mz_gemm<<<dim3((NN + ROWS_PER_BLK - 1) / ROWS_PER_BLK, MP), 256>>>(x, W);

    // per-metapath sequential: keeps h[mp] (25.6 MB) L2-resident during gather
    for (int mp = 0; mp < MP; mp++) {
        mz_gather<<<(NN + 7) / 8, 256>>>(out, mp);
    }
}

// round 7
// speedup vs baseline: 1.5472x; 1.0018x over previous
#include <cuda_runtime.h>
#include <cstdint>

#define NN 100000
#define NE 1000000
#define D  64
#define MP 3

#define TILE 2048
#define NT ((NN + TILE - 1) / TILE)

// Scratch (__device__ globals per allocation-free rule)
__device__ float mg_h[(size_t)MP * NN * D];     // transformed features (76.8 MB)
__device__ float mg_deg[MP * NN];               // deg -> dinv in place
__device__ int   mg_count[MP * NN];             // edges per dest node
__device__ int   mg_off[MP * NN];               // CSR start offsets
__device__ int   mg_ctr[MP * NN];               // running fill cursors
__device__ int2  mg_edge[(size_t)MP * NE];      // packed (src row, norm bits)
__device__ int   mg_tiletot[MP * NT];
__device__ int   mg_tileoff[MP * NT];
__device__ int   mg_sh;                         // 0 = int32 idx, 1 = int64

// ---------------------------------------------------------------------------
// Fused: zero count/deg everywhere; block 0 warp 0 also sniffs edge dtype.
// ---------------------------------------------------------------------------
__global__ void mz_init(const int* __restrict__ ei32) {
    int i = blockIdx.x * blockDim.x + threadIdx.x;
    if (i < MP * NN) { mg_count[i] = 0; mg_deg[i] = 0.f; }
    if (blockIdx.x == 0 && threadIdx.x < 32) {
        int t = threadIdx.x;
        int nz = 0;
        for (int k = 0; k < 8; k++) {
            int s = (t * 8 + k) * 1009;
            nz |= (ei32[2 * s + 1] != 0);
        }
        unsigned b = __ballot_sync(0xffffffffu, nz);
        if (t == 0) mg_sh = (b == 0u) ? 1 : 0;
    }
}

__device__ __forceinline__ int ld_idx(const int* p, size_t pos, int sh) {
    return p[pos << sh];
}

// ---------------------------------------------------------------------------
// Fused: count[col]++ (int) and deg[col] += ew (f32)
// ---------------------------------------------------------------------------
__global__ void mz_hist(const int* __restrict__ ei32,
                        const float* __restrict__ ew) {
    int mp = blockIdx.y;
    int sh = mg_sh;
    size_t colbase = (size_t)mp * 2 * NE + NE;
    const float* ewp = ew + (size_t)mp * NE;
    int* cnt = mg_count + (size_t)mp * NN;
    float* deg = mg_deg + (size_t)mp * NN;
    int stride = gridDim.x * blockDim.x;
    for (int e = blockIdx.x * blockDim.x + threadIdx.x; e < NE; e += stride) {
        int c = ld_idx(ei32, colbase + e, sh);
        atomicAdd(cnt + c, 1);
        atomicAdd(deg + c, ewp[e]);
    }
}

// ---------------------------------------------------------------------------
// Phase A of decoupled scan, fused with deg->dinv for this tile's nodes.
// ---------------------------------------------------------------------------
__global__ __launch_bounds__(256) void mz_scanA() {
    __shared__ int wtot[8];
    __shared__ int wpre[8];
    int mp = blockIdx.y;
    int tile = blockIdx.x;
    int t = threadIdx.x;
    int lane = t & 31;
    int warp = t >> 5;
    const int* cnt = mg_count + (size_t)mp * NN;
    int* off = mg_off + (size_t)mp * NN;
    float* deg = mg_deg + (size_t)mp * NN;

    int base = tile * TILE + t * 8;
    int v[8];
#pragma unroll
    for (int k = 0; k < 8; k++) {
        int i = base + k;
        v[k] = (i < NN) ? cnt[i] : 0;
    }
    // fused dinv on this tile
#pragma unroll
    for (int k = 0; k < 8; k++) {
        int i = base + k;
        if (i < NN) {
            float d = deg[i];
            deg[i] = (d > 0.f) ? rsqrtf(d) : 0.f;
        }
    }
    int mysum = 0;
#pragma unroll
    for (int k = 0; k < 8; k++) mysum += v[k];

    int inc = mysum;
#pragma unroll
    for (int o = 1; o < 32; o <<= 1) {
        int n = __shfl_up_sync(0xffffffffu, inc, o);
        if (lane >= o) inc += n;
    }
    if (lane == 31) wtot[warp] = inc;
    __syncthreads();
    if (t == 0) {
        int run = 0;
#pragma unroll
        for (int w = 0; w < 8; w++) { wpre[w] = run; run += wtot[w]; }
        mg_tiletot[mp * NT + tile] = run;
    }
    __syncthreads();

    int excl = wpre[warp] + inc - mysum;
#pragma unroll
    for (int k = 0; k < 8; k++) {
        int i = base + k;
        if (i < NN) off[i] = excl;
        excl += v[k];
    }
}

__global__ __launch_bounds__(64) void mz_scanB() {
    __shared__ int s[64];
    int mp = blockIdx.x;
    int t = threadIdx.x;
    s[t] = (t < NT) ? mg_tiletot[mp * NT + t] : 0;
    __syncthreads();
    for (int d2 = 1; d2 < 64; d2 <<= 1) {
        int add = (t >= d2) ? s[t - d2] : 0;
        __syncthreads();
        s[t] += add;
        __syncthreads();
    }
    if (t < NT) mg_tileoff[mp * NT + t] = s[t] - mg_tiletot[mp * NT + t];
}

__global__ __launch_bounds__(256) void mz_scanC() {
    int mp = blockIdx.y;
    int tile = blockIdx.x;
    int t = threadIdx.x;
    int toff = mg_tileoff[mp * NT + tile];
    int* off = mg_off + (size_t)mp * NN;
    int* ctr = mg_ctr + (size_t)mp * NN;
    int base = tile * TILE + t * 8;
#pragma unroll
    for (int k = 0; k < 8; k++) {
        int i = base + k;
        if (i < NN) {
            int v = off[i] + toff;
            off[i] = v;
            ctr[i] = v;
        }
    }
}

// ---------------------------------------------------------------------------
// h[mp] = x @ W[mp]  (float4 LDS inner loop: 1 LDS.128 per 4 FFMA)
// ---------------------------------------------------------------------------
#define ROWS_PER_BLK 128

__global__ __launch_bounds__(256) void mz_gemm(const float* __restrict__ x,
                                               const float* __restrict__ W) {
    __shared__ float sW[D * D];
    __shared__ float sx[ROWS_PER_BLK][D];
    int mp = blockIdx.y;
    int t = threadIdx.x;

    const float* Wm = W + (size_t)mp * D * D;
    for (int i = t; i < D * D; i += 256) sW[i] = Wm[i];
    __syncthreads();

    int d = t & 63;
    int r0 = t >> 6;
    float wcol[D];
#pragma unroll
    for (int k = 0; k < D; k++) wcol[k] = sW[k * D + d];

    int rowbase = blockIdx.x * ROWS_PER_BLK;
    const float4* x4 = (const float4*)(x + (size_t)rowbase * D);
    float4* sx4 = (float4*)sx;
    for (int i = t; i < ROWS_PER_BLK * D / 4; i += 256) {
        int row = rowbase + (i >> 4);
        if (row < NN) sx4[i] = x4[i];
    }
    __syncthreads();

    float* hout = mg_h + (size_t)mp * NN * D;
    for (int r = r0; r < ROWS_PER_BLK; r += 4) {
        int row = rowbase + r;
        if (row >= NN) break;
        const float4* xr4 = (const float4*)sx[r];
        float acc = 0.f;
#pragma unroll
        for (int k = 0; k < D / 4; k++) {
            float4 xv = xr4[k];                 // LDS.128 broadcast
            acc = fmaf(xv.x, wcol[4 * k + 0], acc);
            acc = fmaf(xv.y, wcol[4 * k + 1], acc);
            acc = fmaf(xv.z, wcol[4 * k + 2], acc);
            acc = fmaf(xv.w, wcol[4 * k + 3], acc);
        }
        hout[(size_t)row * D + d] = acc;
    }
}

// ---------------------------------------------------------------------------
// Bin edges: packed (row, norm) with norm fully precomputed.
// ---------------------------------------------------------------------------
__global__ void mz_fill(const int* __restrict__ ei32,
                        const float* __restrict__ ew) {
    int mp = blockIdx.y;
    int sh = mg_sh;
    size_t rowbase = (size_t)mp * 2 * NE;
    size_t colbase = rowbase + NE;
    const float* ewp = ew + (size_t)mp * NE;
    const float* dinv = mg_deg + (size_t)mp * NN;
    int* ctr = mg_ctr + (size_t)mp * NN;
    int2* edges = mg_edge + (size_t)mp * NE;
    int stride = gridDim.x * blockDim.x;
    for (int e = blockIdx.x * blockDim.x + threadIdx.x; e < NE; e += stride) {
        int r = ld_idx(ei32, rowbase + e, sh);
        int c = ld_idx(ei32, colbase + e, sh);
        float nm = dinv[r] * ewp[e] * dinv[c];
        int pos = atomicAdd(ctr + c, 1);
        edges[pos] = make_int2(r, __float_as_int(nm));
    }
}

// ---------------------------------------------------------------------------
// Gather: warp per dest node; 4-wide unroll; fused ReLU.
// ---------------------------------------------------------------------------
__global__ __launch_bounds__(256) void mz_gather(float* __restrict__ out,
                                                 int mp) {
    int node = blockIdx.x * 8 + (threadIdx.x >> 5);
    if (node >= NN) return;
    int lane = threadIdx.x & 31;
    const float* h = mg_h + (size_t)mp * NN * D;
    int start = mg_off[(size_t)mp * NN + node];
    int n = mg_count[(size_t)mp * NN + node];
    const int2* edges = mg_edge + (size_t)mp * NE + start;

    float2 acc = make_float2(0.f, 0.f);
    int j = 0;
    for (; j + 4 <= n; j += 4) {
        int2 e0 = edges[j], e1 = edges[j + 1], e2 = edges[j + 2], e3 = edges[j + 3];
        float2 v0 = *(const float2*)(h + (size_t)e0.x * D + lane * 2);
        float2 v1 = *(const float2*)(h + (size_t)e1.x * D + lane * 2);
        float2 v2 = *(const float2*)(h + (size_t)e2.x * D + lane * 2);
        float2 v3 = *(const float2*)(h + (size_t)e3.x * D + lane * 2);
        float n0 = __int_as_float(e0.y), n1 = __int_as_float(e1.y);
        float n2 = __int_as_float(e2.y), n3 = __int_as_float(e3.y);
        acc.x = fmaf(v0.x, n0, acc.x); acc.y = fmaf(v0.y, n0, acc.y);
        acc.x = fmaf(v1.x, n1, acc.x); acc.y = fmaf(v1.y, n1, acc.y);
        acc.x = fmaf(v2.x, n2, acc.x); acc.y = fmaf(v2.y, n2, acc.y);
        acc.x = fmaf(v3.x, n3, acc.x); acc.y = fmaf(v3.y, n3, acc.y);
    }
    for (; j < n; j++) {
        int2 e = edges[j];
        float nm = __int_as_float(e.y);
        float2 v = *(const float2*)(h + (size_t)e.x * D + lane * 2);
        acc.x = fmaf(v.x, nm, acc.x);
        acc.y = fmaf(v.y, nm, acc.y);
    }
    float2 o;
    o.x = fmaxf(acc.x, 0.f);
    o.y = fmaxf(acc.y, 0.f);
    *(float2*)(out + (size_t)mp * NN * D + (size_t)node * D + lane * 2) = o;
}

// ---------------------------------------------------------------------------
extern "C" void kernel_launch(void* const* d_in, const int* in_sizes, int n_in,
                              void* d_out, int out_size) {
    const float* x = (const float*)d_in[0];
    const float* W = (const float*)d_in[1];
    const int* ei32 = (const int*)d_in[2];
    const float* ew = (const float*)d_in[3];
    float* out = (float*)d_out;

    mz_init<<<(MP * NN + 255) / 256, 256>>>(ei32);            // #1
    mz_hist<<<dim3(512, MP), 256>>>(ei32, ew);                // #2
    mz_scanA<<<dim3(NT, MP), 256>>>();                        // #3 (scan + dinv)
    mz_gemm<<<dim3((NN + ROWS_PER_BLK - 1) / ROWS_PER_BLK, MP), 256>>>(x, W); // #4 (profiled)
    mz_scanB<<<MP, 64>>>();                                   // #5
    mz_scanC<<<dim3(NT, MP), 256>>>();                        // #6
    mz_fill<<<dim3(512, MP), 256>>>(ei32, ew);                // #7
    for (int mp = 0; mp < MP; mp++) {                         // #8-10
        mz_gather<<<(NN + 7) / 8, 256>>>(out, mp);
    }
}

// round 9
// speedup vs baseline: 1.9629x; 1.2686x over previous
#include <cuda_runtime.h>
#include <cstdint>

#define NN 100000
#define NE 1000000
#define D  64
#define MP 3

#define TILE 2048
#define NT ((NN + TILE - 1) / TILE)

// Scratch (__device__ globals per allocation-free rule)
__device__ float mg_h[(size_t)MP * NN * D];     // transformed features (76.8 MB)
__device__ float mg_deg[MP * NN];               // deg -> dinv in place
__device__ int   mg_count[MP * NN];             // edges per dest node
__device__ int   mg_off[MP * NN];               // CSR start offsets
__device__ int   mg_ctr[MP * NN];               // running fill cursors
__device__ int2  mg_edge[(size_t)MP * NE];      // packed (src row, norm bits)
__device__ int   mg_tiletot[MP * NT];
__device__ int   mg_tileoff[MP * NT];
__device__ int   mg_sh;                         // 0 = int32 idx, 1 = int64

// ---------------------------------------------------------------------------
// Fused: zero count/deg; block 0 warp 0 sniffs edge dtype.
// ---------------------------------------------------------------------------
__global__ void mz_init(const int* __restrict__ ei32) {
    int i = blockIdx.x * blockDim.x + threadIdx.x;
    if (i < MP * NN) { mg_count[i] = 0; mg_deg[i] = 0.f; }
    if (blockIdx.x == 0 && threadIdx.x < 32) {
        int t = threadIdx.x;
        int nz = 0;
        for (int k = 0; k < 8; k++) {
            int s = (t * 8 + k) * 1009;
            nz |= (ei32[2 * s + 1] != 0);
        }
        unsigned b = __ballot_sync(0xffffffffu, nz);
        if (t == 0) mg_sh = (b == 0u) ? 1 : 0;
    }
}

__device__ __forceinline__ int ld_idx(const int* p, size_t pos, int sh) {
    return p[pos << sh];
}

__global__ void mz_hist(const int* __restrict__ ei32,
                        const float* __restrict__ ew) {
    int mp = blockIdx.y;
    int sh = mg_sh;
    size_t colbase = (size_t)mp * 2 * NE + NE;
    const float* ewp = ew + (size_t)mp * NE;
    int* cnt = mg_count + (size_t)mp * NN;
    float* deg = mg_deg + (size_t)mp * NN;
    int stride = gridDim.x * blockDim.x;
    for (int e = blockIdx.x * blockDim.x + threadIdx.x; e < NE; e += stride) {
        int c = ld_idx(ei32, colbase + e, sh);
        atomicAdd(cnt + c, 1);
        atomicAdd(deg + c, ewp[e]);
    }
}

// ---------------------------------------------------------------------------
// Phase A of decoupled scan, fused with deg->dinv.
// ---------------------------------------------------------------------------
__global__ __launch_bounds__(256) void mz_scanA() {
    __shared__ int wtot[8];
    __shared__ int wpre[8];
    int mp = blockIdx.y;
    int tile = blockIdx.x;
    int t = threadIdx.x;
    int lane = t & 31;
    int warp = t >> 5;
    const int* cnt = mg_count + (size_t)mp * NN;
    int* off = mg_off + (size_t)mp * NN;
    float* deg = mg_deg + (size_t)mp * NN;

    int base = tile * TILE + t * 8;
    int v[8];
#pragma unroll
    for (int k = 0; k < 8; k++) {
        int i = base + k;
        v[k] = (i < NN) ? cnt[i] : 0;
    }
#pragma unroll
    for (int k = 0; k < 8; k++) {
        int i = base + k;
        if (i < NN) {
            float d = deg[i];
            deg[i] = (d > 0.f) ? rsqrtf(d) : 0.f;
        }
    }
    int mysum = 0;
#pragma unroll
    for (int k = 0; k < 8; k++) mysum += v[k];

    int inc = mysum;
#pragma unroll
    for (int o = 1; o < 32; o <<= 1) {
        int n = __shfl_up_sync(0xffffffffu, inc, o);
        if (lane >= o) inc += n;
    }
    if (lane == 31) wtot[warp] = inc;
    __syncthreads();
    if (t == 0) {
        int run = 0;
#pragma unroll
        for (int w = 0; w < 8; w++) { wpre[w] = run; run += wtot[w]; }
        mg_tiletot[mp * NT + tile] = run;
    }
    __syncthreads();

    int excl = wpre[warp] + inc - mysum;
#pragma unroll
    for (int k = 0; k < 8; k++) {
        int i = base + k;
        if (i < NN) off[i] = excl;
        excl += v[k];
    }
}

__global__ __launch_bounds__(64) void mz_scanB() {
    __shared__ int s[64];
    int mp = blockIdx.x;
    int t = threadIdx.x;
    s[t] = (t < NT) ? mg_tiletot[mp * NT + t] : 0;
    __syncthreads();
    for (int d2 = 1; d2 < 64; d2 <<= 1) {
        int add = (t >= d2) ? s[t - d2] : 0;
        __syncthreads();
        s[t] += add;
        __syncthreads();
    }
    if (t < NT) mg_tileoff[mp * NT + t] = s[t] - mg_tiletot[mp * NT + t];
}

__global__ __launch_bounds__(256) void mz_scanC() {
    int mp = blockIdx.y;
    int tile = blockIdx.x;
    int t = threadIdx.x;
    int toff = mg_tileoff[mp * NT + tile];
    int* off = mg_off + (size_t)mp * NN;
    int* ctr = mg_ctr + (size_t)mp * NN;
    int base = tile * TILE + t * 8;
#pragma unroll
    for (int k = 0; k < 8; k++) {
        int i = base + k;
        if (i < NN) {
            int v = off[i] + toff;
            off[i] = v;
            ctr[i] = v;
        }
    }
}

// ---------------------------------------------------------------------------
// GEMM via mma.sync.m16n8k8 tf32 (sm_80+ path, no 'a' features needed).
// Block: 256 thr = 8 warps x 16 rows = 128-row tile; all 3 mp per block.
// smem: x tile padded to 68 floats/row; W padded to 72 floats/row
// (both paddings make the fragment LDS patterns bank-conflict-free).
// ---------------------------------------------------------------------------
#define XPAD 68
#define WPAD 72
#define SX_FLOATS (128 * XPAD)
#define SW_FLOATS (MP * 64 * WPAD)
#define GEMM_SMEM ((SX_FLOATS + SW_FLOATS) * 4)

__device__ __forceinline__ uint32_t f2tf32(float f) {
    uint32_t u;
    asm("cvt.rna.tf32.f32 %0, %1;" : "=r"(u) : "f"(f));
    return u;
}

__global__ __launch_bounds__(256) void mz_gemm_mma(const float* __restrict__ x,
                                                   const float* __restrict__ W) {
    extern __shared__ float smem[];
    float* sx = smem;                 // [128][XPAD]
    float* sW = smem + SX_FLOATS;     // [MP][64][WPAD]
    int t = threadIdx.x;
    int wid = t >> 5;
    int lane = t & 31;
    int rowbase = blockIdx.x * 128;

    // Stage x tile (tf32-rounded)
    const float4* x4 = (const float4*)x;
    for (int i = t; i < 2048; i += 256) {
        int row = i >> 4;
        int q = i & 15;
        float4 v = make_float4(0.f, 0.f, 0.f, 0.f);
        int grow = rowbase + row;
        if (grow < NN) v = x4[(size_t)grow * 16 + q];
        uint4 u = make_uint4(f2tf32(v.x), f2tf32(v.y), f2tf32(v.z), f2tf32(v.w));
        *(uint4*)(sx + row * XPAD + q * 4) = u;
    }
    // Stage all 3 W (tf32-rounded)
    const float4* W4 = (const float4*)W;
    for (int i = t; i < MP * 64 * 16; i += 256) {
        int mp = i >> 10;
        int rem = i & 1023;
        int k = rem >> 4;
        int q = rem & 15;
        float4 v = W4[i];
        uint4 u = make_uint4(f2tf32(v.x), f2tf32(v.y), f2tf32(v.z), f2tf32(v.w));
        *(uint4*)(sW + mp * 64 * WPAD + k * WPAD + q * 4) = u;
    }
    __syncthreads();

    int r = lane >> 2;                // 0..7
    int c = lane & 3;                 // 0..3
    const uint32_t* sxu = (const uint32_t*)sx;
    const uint32_t* sWu = (const uint32_t*)sW;

    // A fragments for this warp's 16 rows, all 8 k-steps (32 regs)
    uint32_t a[8][4];
    int ar0 = (wid * 16 + r) * XPAD;
    int ar1 = (wid * 16 + r + 8) * XPAD;
#pragma unroll
    for (int kk = 0; kk < 8; kk++) {
        int kc = kk * 8 + c;
        a[kk][0] = sxu[ar0 + kc];
        a[kk][1] = sxu[ar1 + kc];
        a[kk][2] = sxu[ar0 + kc + 4];
        a[kk][3] = sxu[ar1 + kc + 4];
    }

    int row0 = rowbase + wid * 16 + r;
#pragma unroll
    for (int mp = 0; mp < MP; mp++) {
        const uint32_t* wp = sWu + mp * 64 * WPAD;
        float d[8][4];
#pragma unroll
        for (int nt = 0; nt < 8; nt++) {
            d[nt][0] = 0.f; d[nt][1] = 0.f; d[nt][2] = 0.f; d[nt][3] = 0.f;
        }
#pragma unroll
        for (int kk = 0; kk < 8; kk++) {
            int kb = (kk * 8 + c) * WPAD + r;   // B frag: k = kk*8+c, n = nt*8+r
#pragma unroll
            for (int nt = 0; nt < 8; nt++) {
                uint32_t b0 = wp[kb + nt * 8];
                uint32_t b1 = wp[kb + 4 * WPAD + nt * 8];
                asm volatile(
                    "mma.sync.aligned.m16n8k8.row.col.f32.tf32.tf32.f32 "
                    "{%0,%1,%2,%3}, {%4,%5,%6,%7}, {%8,%9}, {%0,%1,%2,%3};"
                    : "+f"(d[nt][0]), "+f"(d[nt][1]), "+f"(d[nt][2]), "+f"(d[nt][3])
                    : "r"(a[kk][0]), "r"(a[kk][1]), "r"(a[kk][2]), "r"(a[kk][3]),
                      "r"(b0), "r"(b1));
            }
        }
        float* hout = mg_h + (size_t)mp * NN * D;
        if (row0 < NN) {
            float2* dst = (float2*)(hout + (size_t)row0 * D);
#pragma unroll
            for (int nt = 0; nt < 8; nt++)
                dst[nt * 4 + c] = make_float2(d[nt][0], d[nt][1]);
        }
        if (row0 + 8 < NN) {
            float2* dst = (float2*)(hout + (size_t)(row0 + 8) * D);
#pragma unroll
            for (int nt = 0; nt < 8; nt++)
                dst[nt * 4 + c] = make_float2(d[nt][2], d[nt][3]);
        }
    }
}

// ---------------------------------------------------------------------------
// Bin edges: packed (row, norm), norm precomputed.
// ---------------------------------------------------------------------------
__global__ void mz_fill(const int* __restrict__ ei32,
                        const float* __restrict__ ew) {
    int mp = blockIdx.y;
    int sh = mg_sh;
    size_t rowbase = (size_t)mp * 2 * NE;
    size_t colbase = rowbase + NE;
    const float* ewp = ew + (size_t)mp * NE;
    const float* dinv = mg_deg + (size_t)mp * NN;
    int* ctr = mg_ctr + (size_t)mp * NN;
    int2* edges = mg_edge + (size_t)mp * NE;
    int stride = gridDim.x * blockDim.x;
    for (int e = blockIdx.x * blockDim.x + threadIdx.x; e < NE; e += stride) {
        int r = ld_idx(ei32, rowbase + e, sh);
        int c = ld_idx(ei32, colbase + e, sh);
        float nm = dinv[r] * ewp[e] * dinv[c];
        int pos = atomicAdd(ctr + c, 1);
        edges[pos] = make_int2(r, __float_as_int(nm));
    }
}

// ---------------------------------------------------------------------------
// Gather: warp per dest node; 4-wide unroll; fused ReLU.
// ---------------------------------------------------------------------------
__global__ __launch_bounds__(256) void mz_gather(float* __restrict__ out,
                                                 int mp) {
    int node = blockIdx.x * 8 + (threadIdx.x >> 5);
    if (node >= NN) return;
    int lane = threadIdx.x & 31;
    const float* h = mg_h + (size_t)mp * NN * D;
    int start = mg_off[(size_t)mp * NN + node];
    int n = mg_count[(size_t)mp * NN + node];
    const int2* edges = mg_edge + (size_t)mp * NE + start;

    float2 acc = make_float2(0.f, 0.f);
    int j = 0;
    for (; j + 4 <= n; j += 4) {
        int2 e0 = edges[j], e1 = edges[j + 1], e2 = edges[j + 2], e3 = edges[j + 3];
        float2 v0 = *(const float2*)(h + (size_t)e0.x * D + lane * 2);
        float2 v1 = *(const float2*)(h + (size_t)e1.x * D + lane * 2);
        float2 v2 = *(const float2*)(h + (size_t)e2.x * D + lane * 2);
        float2 v3 = *(const float2*)(h + (size_t)e3.x * D + lane * 2);
        float n0 = __int_as_float(e0.y), n1 = __int_as_float(e1.y);
        float n2 = __int_as_float(e2.y), n3 = __int_as_float(e3.y);
        acc.x = fmaf(v0.x, n0, acc.x); acc.y = fmaf(v0.y, n0, acc.y);
        acc.x = fmaf(v1.x, n1, acc.x); acc.y = fmaf(v1.y, n1, acc.y);
        acc.x = fmaf(v2.x, n2, acc.x); acc.y = fmaf(v2.y, n2, acc.y);
        acc.x = fmaf(v3.x, n3, acc.x); acc.y = fmaf(v3.y, n3, acc.y);
    }
    for (; j < n; j++) {
        int2 e = edges[j];
        float nm = __int_as_float(e.y);
        float2 v = *(const float2*)(h + (size_t)e.x * D + lane * 2);
        acc.x = fmaf(v.x, nm, acc.x);
        acc.y = fmaf(v.y, nm, acc.y);
    }
    float2 o;
    o.x = fmaxf(acc.x, 0.f);
    o.y = fmaxf(acc.y, 0.f);
    *(float2*)(out + (size_t)mp * NN * D + (size_t)node * D + lane * 2) = o;
}

// ---------------------------------------------------------------------------
extern "C" void kernel_launch(void* const* d_in, const int* in_sizes, int n_in,
                              void* d_out, int out_size) {
    const float* x = (const float*)d_in[0];
    const float* W = (const float*)d_in[1];
    const int* ei32 = (const int*)d_in[2];
    const float* ew = (const float*)d_in[3];
    float* out = (float*)d_out;

    cudaFuncSetAttribute(mz_gemm_mma, cudaFuncAttributeMaxDynamicSharedMemorySize,
                         GEMM_SMEM);

    mz_init<<<(MP * NN + 255) / 256, 256>>>(ei32);            // #1
    mz_hist<<<dim3(512, MP), 256>>>(ei32, ew);                // #2
    mz_scanA<<<dim3(NT, MP), 256>>>();                        // #3
    mz_gemm_mma<<<(NN + 127) / 128, 256, GEMM_SMEM>>>(x, W);  // #4 (profiled)
    mz_scanB<<<MP, 64>>>();                                   // #5
    mz_scanC<<<dim3(NT, MP), 256>>>();                        // #6
    mz_fill<<<dim3(512, MP), 256>>>(ei32, ew);                // #7
    for (int mp = 0; mp < MP; mp++) {                         // #8-10
        mz_gather<<<(NN + 7) / 8, 256>>>(out, mp);
    }
}